// round 9
// baseline (speedup 1.0000x reference)
#include <cuda_runtime.h>
#include <cuda.h>
#include <cuda_bf16.h>
#include <math.h>
#include <stdint.h>

// ===========================================================================
// R8: tail elimination. Engine unchanged from R6/R7 (bf16x3 mma.sync + TMA).
//  - 3 fold GEMMs batched into one z=3 launch (V3 computed transposed).
//  - output GEMM split-K=2 via blockIdx.z + fp32 partial reduce.
// ===========================================================================

#define TILE_B 8192              // one 128x32 bf16 tile in smem (bytes)
#define STAGE_B 32768            // 4 tiles (Ah,Al,Bh,Bl)
#define SMEM_TOT (1024 + 1024 + 3 * STAGE_B)

__device__ __forceinline__ uint32_t smem_u32(const void* p) {
    uint32_t a;
    asm("{ .reg .u64 t; cvta.to.shared.u64 t, %1; cvt.u32.u64 %0, t; }" : "=r"(a) : "l"(p));
    return a;
}
#define MBARRIER_INIT(a, c) \
    asm volatile("mbarrier.init.shared.b64 [%0], %1;" :: "r"((uint32_t)(a)), "r"((uint32_t)(c)) : "memory")
#define MBARRIER_EXPECT_TX(a, b) \
    asm volatile("mbarrier.arrive.expect_tx.shared.b64 _, [%0], %1;" :: "r"((uint32_t)(a)), "r"((uint32_t)(b)) : "memory")
#define MBARRIER_WAIT_PARITY(a, p) do { \
    uint32_t _m = (uint32_t)(a), _p = (uint32_t)(p), _d; \
    asm volatile("{\n\t.reg .pred q;\n\t" \
        "mbarrier.try_wait.parity.acquire.cta.shared::cta.b64 q, [%1], %2;\n\t" \
        "selp.b32 %0, 1, 0, q;\n\t}" : "=r"(_d) : "r"(_m), "r"(_p) : "memory"); \
    if (!_d) { \
        asm volatile("{\n\t.reg .pred Q;\n\t" \
            "WL_%=:\n\t" \
            "mbarrier.try_wait.parity.acquire.cta.shared::cta.b64 Q, [%0], %1, 0x989680;\n\t" \
            "@Q bra.uni WD_%=;\n\t" \
            "bra.uni WL_%=;\n\t" \
            "WD_%=:\n\t}" :: "r"(_m), "r"(_p) : "memory"); \
    } \
} while (0)
#define TMA_LOAD_3D(sa, tm, cx, cy, cz, mb) \
    asm volatile("cp.async.bulk.tensor.3d.shared::cta.global.tile.mbarrier::complete_tx::bytes " \
        "[%0], [%1, {%2, %3, %4}], [%5];" \
        :: "r"((uint32_t)(sa)), "l"(tm), "r"((int32_t)(cx)), "r"((int32_t)(cy)), \
           "r"((int32_t)(cz)), "r"((uint32_t)(mb)) : "memory")
#define LDSM4(R, a) \
    asm volatile("ldmatrix.sync.aligned.m8n8.x4.shared.b16 {%0,%1,%2,%3}, [%4];" \
        : "=r"((R)[0]), "=r"((R)[1]), "=r"((R)[2]), "=r"((R)[3]) : "r"(a))

__device__ __forceinline__ void mma_bf16(float* c, const uint32_t* a, uint32_t b0, uint32_t b1) {
    asm volatile(
        "mma.sync.aligned.m16n8k16.row.col.f32.bf16.bf16.f32 "
        "{%0,%1,%2,%3}, {%4,%5,%6,%7}, {%8,%9}, {%0,%1,%2,%3};"
        : "+f"(c[0]), "+f"(c[1]), "+f"(c[2]), "+f"(c[3])
        : "r"(a[0]), "r"(a[1]), "r"(a[2]), "r"(a[3]), "r"(b0), "r"(b1));
}

// 16B-granular XOR swizzle within a [rows x 32] bf16 tile (64B rows).
// Identical to TMA CU_TENSOR_MAP_SWIZZLE_64B layout for 64B-wide boxes.
__device__ __forceinline__ uint32_t sw(int row, int col16) {
    return (uint32_t)(row * 64 + ((col16 ^ ((row >> 1) & 3)) << 4));
}

// EPI 0: split-write (Ch,Cl bf16).  EPI 1: fp32 write Cf.
// EPI 2: v = OTH * silu(acc), split-write.
// czs: z-stride (elements) applied to C pointers.
// kz:  if nonzero, z selects a K-chunk of length kz (split-K); else z is a
//      batch index fed to the TMA z-coordinate.
template <int EPI>
__global__ __launch_bounds__(256, 2) void gemm_b3(
    const __grid_constant__ CUtensorMap tAh, const __grid_constant__ CUtensorMap tAl,
    const __grid_constant__ CUtensorMap tBh, const __grid_constant__ CUtensorMap tBl,
    float* __restrict__ Cf, __nv_bfloat16* __restrict__ Ch, __nv_bfloat16* __restrict__ Cl,
    const float* __restrict__ OTH, int M, int N, int K,
    long long czs, int kz)
{
    extern __shared__ char smem[];
    const uint32_t sb0 = smem_u32(smem);
    const uint32_t sb = (sb0 + 1023) & ~1023u;   // 1KB-align for TMA swizzle
    const int tid = threadIdx.x;
    const int z = blockIdx.z;
    const int k00 = kz ? z * kz : 0;
    const int cz = kz ? 0 : z;
    const int Keff = kz ? kz : K;

    if (Cf) Cf += (size_t)z * czs;
    if (Ch) Ch += (size_t)z * czs;
    if (Cl) Cl += (size_t)z * czs;

    // ---- L2-friendly CTA rasterization (GROUP_M = 16), per z-slice ----
    const int gn = gridDim.x, gm = gridDim.y;
    const int bid = blockIdx.y * gn + blockIdx.x;
    const int npg = 16 * gn;
    const int gid = bid / npg;
    const int fm = gid * 16;
    const int gs = (gm - fm < 16) ? (gm - fm) : 16;
    const int bm = (fm + (bid % gs)) * 128;
    const int bn = ((bid % npg) / gs) * 128;

    const int w = tid >> 5, lane = tid & 31;
    const int wm = (w >> 2) * 64, wn = (w & 3) * 32;
    const int jj = lane >> 3, rr = lane & 7;
    const int aR = (jj & 1) * 8 + rr, aC16 = jj >> 1;   // A: (m0k0)(m8k0)(m0k8)(m8k8)
    const int bR = (jj >> 1) * 8 + rr, bC16 = jj & 1;   // B: (n0k0)(n0k8)(n8k0)(n8k8)

    const uint32_t bars = sb;                 // 3 x 8B mbarriers
    const uint32_t stg0 = sb + 1024;          // 3 x 32KB stages

    if (tid == 0) {
        MBARRIER_INIT(bars + 0, 1);
        MBARRIER_INIT(bars + 8, 1);
        MBARRIER_INIT(bars + 16, 1);
    }
    __syncthreads();

    const int nst = Keff / 32;

    // prologue: issue stages 0..2
    if (tid == 0) {
#pragma unroll
        for (int s = 0; s < 3; s++) {
            const uint32_t bar = bars + s * 8;
            const uint32_t stb = stg0 + s * STAGE_B;
            const int k0 = k00 + s * 32;
            MBARRIER_EXPECT_TX(bar, STAGE_B);
            TMA_LOAD_3D(stb,              &tAh, k0, bm, cz, bar);
            TMA_LOAD_3D(stb + TILE_B,     &tAl, k0, bm, cz, bar);
            TMA_LOAD_3D(stb + 2 * TILE_B, &tBh, k0, bn, cz, bar);
            TMA_LOAD_3D(stb + 3 * TILE_B, &tBl, k0, bn, cz, bar);
        }
    }

    float c[4][4][4];
#pragma unroll
    for (int mi = 0; mi < 4; mi++)
#pragma unroll
        for (int ni = 0; ni < 4; ni++)
#pragma unroll
            for (int q = 0; q < 4; q++) c[mi][ni][q] = 0.0f;

    for (int t = 0; t < nst; t++) {
        const int buf = t % 3;
        MBARRIER_WAIT_PARITY(bars + buf * 8, (t / 3) & 1);

        const uint32_t stb = stg0 + (uint32_t)buf * STAGE_B;
#pragma unroll
        for (int ks = 0; ks < 2; ks++) {
            uint32_t af[4][4], bhf[2][4], blf[2][4];
            // A-hi frags
#pragma unroll
            for (int mi = 0; mi < 4; mi++)
                LDSM4(af[mi], stb + sw(wm + mi * 16 + aR, ks * 2 + aC16));
            // B-hi / B-lo frags
#pragma unroll
            for (int np = 0; np < 2; np++) {
                const uint32_t bd = stb + 2 * TILE_B + sw(wn + np * 16 + bR, ks * 2 + bC16);
                LDSM4(bhf[np], bd);
                LDSM4(blf[np], bd + TILE_B);
            }
            // hh + hl
#pragma unroll
            for (int mi = 0; mi < 4; mi++)
#pragma unroll
                for (int ni = 0; ni < 4; ni++) {
                    const int p = ni >> 1, q = (ni & 1) * 2;
                    mma_bf16(c[mi][ni], af[mi], bhf[p][q], bhf[p][q + 1]);
                    mma_bf16(c[mi][ni], af[mi], blf[p][q], blf[p][q + 1]);
                }
            // A-lo frags overwrite A-hi (reduced liveness)
#pragma unroll
            for (int mi = 0; mi < 4; mi++)
                LDSM4(af[mi], stb + TILE_B + sw(wm + mi * 16 + aR, ks * 2 + aC16));
            // lh
#pragma unroll
            for (int mi = 0; mi < 4; mi++)
#pragma unroll
                for (int ni = 0; ni < 4; ni++) {
                    const int p = ni >> 1, q = (ni & 1) * 2;
                    mma_bf16(c[mi][ni], af[mi], bhf[p][q], bhf[p][q + 1]);
                }
        }

        __syncthreads();   // all warps done reading buf before refill
        if (t + 3 < nst && tid == 0) {
            const uint32_t bar = bars + buf * 8;
            const int k0 = k00 + (t + 3) * 32;
            MBARRIER_EXPECT_TX(bar, STAGE_B);
            TMA_LOAD_3D(stb,              &tAh, k0, bm, cz, bar);
            TMA_LOAD_3D(stb + TILE_B,     &tAl, k0, bm, cz, bar);
            TMA_LOAD_3D(stb + 2 * TILE_B, &tBh, k0, bn, cz, bar);
            TMA_LOAD_3D(stb + 3 * TILE_B, &tBl, k0, bn, cz, bar);
        }
    }

    // ---- epilogue ----
#pragma unroll
    for (int mi = 0; mi < 4; mi++)
#pragma unroll
        for (int ni = 0; ni < 4; ni++) {
            const int r0 = bm + wm + mi * 16 + (lane >> 2);
            const int col = bn + wn + ni * 8 + (lane & 3) * 2;
            const size_t o0 = (size_t)r0 * N + col;
            const size_t o1 = (size_t)(r0 + 8) * N + col;
            float v0 = c[mi][ni][0], v1 = c[mi][ni][1];
            float v2 = c[mi][ni][2], v3 = c[mi][ni][3];
            if (EPI == 2) {
                const float2 u0 = *(const float2*)(OTH + o0);
                const float2 u1 = *(const float2*)(OTH + o1);
                v0 = u0.x * (v0 / (1.0f + expf(-v0)));
                v1 = u0.y * (v1 / (1.0f + expf(-v1)));
                v2 = u1.x * (v2 / (1.0f + expf(-v2)));
                v3 = u1.y * (v3 / (1.0f + expf(-v3)));
            }
            if (EPI == 1) {
                *(float2*)(Cf + o0) = make_float2(v0, v1);
                *(float2*)(Cf + o1) = make_float2(v2, v3);
            } else {
                __nv_bfloat162 hh, ll;
                hh.x = __float2bfloat16(v0); hh.y = __float2bfloat16(v1);
                ll.x = __float2bfloat16(v0 - __bfloat162float(hh.x));
                ll.y = __float2bfloat16(v1 - __bfloat162float(hh.y));
                *(__nv_bfloat162*)(Ch + o0) = hh;
                *(__nv_bfloat162*)(Cl + o0) = ll;
                hh.x = __float2bfloat16(v2); hh.y = __float2bfloat16(v3);
                ll.x = __float2bfloat16(v2 - __bfloat162float(hh.x));
                ll.y = __float2bfloat16(v3 - __bfloat162float(hh.y));
                *(__nv_bfloat162*)(Ch + o1) = hh;
                *(__nv_bfloat162*)(Cl + o1) = ll;
            }
        }
}

// ===========================================================================
// scratch (static; no allocations).
// ===========================================================================
#define MDE 16777216ll
#define FFE 67108864ll
__device__ __nv_bfloat16 g_bf[805306368];
__device__ float g_c1[67108864];

// ---- pre-pass: fp32 -> (bf16 hi, bf16 lo) ----
struct bf4 { __nv_bfloat162 a, b; };
__global__ void split_k(const float4* __restrict__ in, bf4* __restrict__ hi,
                        bf4* __restrict__ lo, int n4) {
    for (int i = blockIdx.x * blockDim.x + threadIdx.x; i < n4; i += gridDim.x * blockDim.x) {
        const float4 v = in[i];
        bf4 H, L;
        H.a.x = __float2bfloat16(v.x); H.a.y = __float2bfloat16(v.y);
        H.b.x = __float2bfloat16(v.z); H.b.y = __float2bfloat16(v.w);
        L.a.x = __float2bfloat16(v.x - __bfloat162float(H.a.x));
        L.a.y = __float2bfloat16(v.y - __bfloat162float(H.a.y));
        L.b.x = __float2bfloat16(v.z - __bfloat162float(H.b.x));
        L.b.y = __float2bfloat16(v.w - __bfloat162float(H.b.y));
        hi[i] = H; lo[i] = L;
    }
}
// rectangular transpose + split: in [R,C] fp32 -> out_{hi,lo} [C,R]
__global__ void tsplit_k(const float* __restrict__ in, __nv_bfloat16* __restrict__ hi,
                         __nv_bfloat16* __restrict__ lo, int R, int C) {
    __shared__ float t[32][33];
    const int c0 = blockIdx.x * 32, r0 = blockIdx.y * 32;
#pragma unroll
    for (int i = 0; i < 32; i += 8)
        t[threadIdx.y + i][threadIdx.x] = in[(size_t)(r0 + threadIdx.y + i) * C + c0 + threadIdx.x];
    __syncthreads();
#pragma unroll
    for (int i = 0; i < 32; i += 8) {
        const float v = t[threadIdx.x][threadIdx.y + i];
        const __nv_bfloat16 h = __float2bfloat16(v);
        const size_t o = (size_t)(c0 + threadIdx.y + i) * R + r0 + threadIdx.x;
        hi[o] = h;
        lo[o] = __float2bfloat16(v - __bfloat162float(h));
    }
}
// bf16 pair transpose: a,b [R,C] -> oa,ob [C,R]
__global__ void tpose2_k(const __nv_bfloat16* __restrict__ a, const __nv_bfloat16* __restrict__ b,
                         __nv_bfloat16* __restrict__ oa, __nv_bfloat16* __restrict__ ob,
                         int R, int C) {
    __shared__ __nv_bfloat16 t[2][32][33];
    const int c0 = blockIdx.x * 32, r0 = blockIdx.y * 32;
#pragma unroll
    for (int i = 0; i < 32; i += 8) {
        const size_t src = (size_t)(r0 + threadIdx.y + i) * C + c0 + threadIdx.x;
        t[0][threadIdx.y + i][threadIdx.x] = a[src];
        t[1][threadIdx.y + i][threadIdx.x] = b[src];
    }
    __syncthreads();
#pragma unroll
    for (int i = 0; i < 32; i += 8) {
        const size_t o = (size_t)(c0 + threadIdx.y + i) * R + r0 + threadIdx.x;
        oa[o] = t[0][threadIdx.x][threadIdx.y + i];
        ob[o] = t[1][threadIdx.x][threadIdx.y + i];
    }
}
// split-K reduce: out[i] = p[i] + p[i + n4]
__global__ void red2_k(const float4* __restrict__ p, float4* __restrict__ o, int n4) {
    for (int i = blockIdx.x * blockDim.x + threadIdx.x; i < n4; i += gridDim.x * blockDim.x) {
        const float4 x = p[i], y = p[i + n4];
        o[i] = make_float4(x.x + y.x, x.y + y.y, x.z + y.z, x.w + y.w);
    }
}

// ===========================================================================
typedef CUresult (*PFN_enc)(CUtensorMap*, CUtensorMapDataType, cuuint32_t, void*,
                            const cuuint64_t*, const cuuint64_t*, const cuuint32_t*,
                            const cuuint32_t*, CUtensorMapInterleave, CUtensorMapSwizzle,
                            CUtensorMapL2promotion, CUtensorMapFloatOOBfill);

static void enc_map(PFN_enc fn, CUtensorMap* m, const __nv_bfloat16* p, int K, int rows,
                    int nz, long long zelems) {
    cuuint64_t dims[3] = {(cuuint64_t)K, (cuuint64_t)rows, (cuuint64_t)nz};
    cuuint64_t str[2] = {(cuuint64_t)K * 2, (cuuint64_t)zelems * 2};
    cuuint32_t box[3] = {32, 128, 1};
    cuuint32_t es[3] = {1, 1, 1};
    fn(m, CU_TENSOR_MAP_DATA_TYPE_BFLOAT16, 3, (void*)p, dims, str, box, es,
       CU_TENSOR_MAP_INTERLEAVE_NONE, CU_TENSOR_MAP_SWIZZLE_64B,
       CU_TENSOR_MAP_L2_PROMOTION_L2_128B, CU_TENSOR_MAP_FLOAT_OOB_FILL_NONE);
}

static void rung(PFN_enc fn, int epi,
                 const __nv_bfloat16* Ah, const __nv_bfloat16* Al,
                 const __nv_bfloat16* Bh, const __nv_bfloat16* Bl,
                 float* Cf, __nv_bfloat16* Ch, __nv_bfloat16* Cl,
                 const float* OTH, int M, int N, int K,
                 int nz, long long zsA, long long zsB, long long czs, int kz, int gz)
{
    CUtensorMap ma, mal, mb, mbl;
    enc_map(fn, &ma, Ah, K, M, nz, zsA);  enc_map(fn, &mal, Al, K, M, nz, zsA);
    enc_map(fn, &mb, Bh, K, N, nz, zsB);  enc_map(fn, &mbl, Bl, K, N, nz, zsB);
    const dim3 g(N / 128, M / 128, gz), b(256);
    if (epi == 0) {
        cudaFuncSetAttribute(gemm_b3<0>, cudaFuncAttributeMaxDynamicSharedMemorySize, SMEM_TOT);
        gemm_b3<0><<<g, b, SMEM_TOT>>>(ma, mal, mb, mbl, Cf, Ch, Cl, OTH, M, N, K, czs, kz);
    } else if (epi == 1) {
        cudaFuncSetAttribute(gemm_b3<1>, cudaFuncAttributeMaxDynamicSharedMemorySize, SMEM_TOT);
        gemm_b3<1><<<g, b, SMEM_TOT>>>(ma, mal, mb, mbl, Cf, Ch, Cl, OTH, M, N, K, czs, kz);
    } else {
        cudaFuncSetAttribute(gemm_b3<2>, cudaFuncAttributeMaxDynamicSharedMemorySize, SMEM_TOT);
        gemm_b3<2><<<g, b, SMEM_TOT>>>(ma, mal, mb, mbl, Cf, Ch, Cl, OTH, M, N, K, czs, kz);
    }
}

extern "C" void kernel_launch(void* const* d_in, const int* in_sizes, int n_in,
                              void* d_out, int out_size)
{
    const float* x  = (const float*)d_in[0];
    const float* wu = (const float*)d_in[1];
    const float* wg = (const float*)d_in[2];
    const float* wd = (const float*)d_in[3];
    const float* h1 = (const float*)d_in[4];   // h_up_T   [F,F]
    const float* h2 = (const float*)d_in[5];   // h_gate_T [F,F]
    const float* h3 = (const float*)d_in[6];   // h_down   [F,F]

    int F = 1;
    while ((long long)(F + 1) * (F + 1) <= (long long)in_sizes[4]) F++;
    const int D = in_sizes[1] / F;
    const int M = in_sizes[0] / D;

    __nv_bfloat16* bb;
    float* C1;
    cudaGetSymbolAddress((void**)&bb, g_bf);
    cudaGetSymbolAddress((void**)&C1, g_c1);

    // slab layout (16 MD-blocks + 8 FF-blocks = 805.3M elems exactly)
    __nv_bfloat16 *xh   = bb,            *xl   = bb + MDE;
    __nv_bfloat16 *wuth = bb + 2 * MDE,  *wutl = bb + 3 * MDE;   // w_up^T   [D,F]
    __nv_bfloat16 *wgth = bb + 4 * MDE,  *wgtl = bb + 5 * MDE;   // w_gate^T [D,F]
    __nv_bfloat16 *wdh  = bb + 6 * MDE,  *wdl  = bb + 7 * MDE;   // w_down   [D,F]
    __nv_bfloat16 *V1h  = bb + 8 * MDE,  *V1l  = bb + 9 * MDE;   // [F,D]
    __nv_bfloat16 *V2h  = bb + 10 * MDE, *V2l  = bb + 11 * MDE;  // [F,D]
    __nv_bfloat16 *V3th = bb + 12 * MDE, *V3tl = bb + 13 * MDE;  // V3^T [F,D]
    __nv_bfloat16* hb = bb + 14 * MDE;
    __nv_bfloat16 *h1th = hb,            *h1tl = hb + FFE;       // h_up_T^T   [F,F]
    __nv_bfloat16 *h2th = hb + 2 * FFE,  *h2tl = hb + 3 * FFE;   // h_gate_T^T [F,F]
    __nv_bfloat16 *hdh  = hb + 4 * FFE,  *hdl  = hb + 5 * FFE;   // h_down     [F,F]
    __nv_bfloat16 *Uh   = hb + 6 * FFE,  *Ul   = hb + 7 * FFE;   // gated      [M,F]
    __nv_bfloat16 *V3h  = hb + 8 * FFE,  *V3l  = hb + 8 * FFE + MDE;  // V3 [D,F]

    // ---- prepass: splits & transpose-splits ----
    split_k<<<2048, 256>>>((const float4*)x,  (bf4*)xh,  (bf4*)xl,  (M * D) / 4);
    split_k<<<2048, 256>>>((const float4*)wd, (bf4*)wdh, (bf4*)wdl, (D * F) / 4);
    split_k<<<2048, 256>>>((const float4*)h3, (bf4*)hdh, (bf4*)hdl, (F * F) / 4);
    const dim3 tb(32, 8);
    tsplit_k<<<dim3(F / 32, F / 32), tb>>>(h1, h1th, h1tl, F, F);
    tsplit_k<<<dim3(F / 32, F / 32), tb>>>(h2, h2th, h2tl, F, F);
    tsplit_k<<<dim3(D / 32, F / 32), tb>>>(wu, wuth, wutl, F, D);
    tsplit_k<<<dim3(D / 32, F / 32), tb>>>(wg, wgth, wgtl, F, D);

    PFN_enc fn = nullptr;
    cudaDriverEntryPointQueryResult qr;
    cudaGetDriverEntryPoint("cuTensorMapEncodeTiled", (void**)&fn, cudaEnableDefault, &qr);

    // ---- batched fold GEMM (z=3): V1 = h1t@wut^T, V2 = h2t@wgt^T, V3^T = hd@wd^T ----
    // A bases h1th/h1tl, z-stride 2*FFE; B bases wuth/wutl, z-stride 2*MDE;
    // C bases V1h/V1l, z-stride 2*MDE.
    rung(fn, 0, h1th, h1tl, wuth, wutl, nullptr, V1h, V1l, nullptr,
         F, D, F, 3, 2 * FFE, 2 * MDE, 2 * MDE, 0, 3);

    // V3 = transpose(V3^T): [F,D] -> [D,F]
    tpose2_k<<<dim3(D / 32, F / 32), tb>>>(V3th, V3tl, V3h, V3l, F, D);

    // ---- activation GEMMs ----
    // up2 = x @ V1^T -> C1 (fp32)
    rung(fn, 1, xh, xl, V1h, V1l, C1, nullptr, nullptr, nullptr,
         M, F, D, 1, (long long)D * F, (long long)D * F, 0, 0, 1);
    // gated = C1 * silu(x @ V2^T) -> split U
    rung(fn, 2, xh, xl, V2h, V2l, nullptr, Uh, Ul, C1,
         M, F, D, 1, (long long)D * M, (long long)D * F, 0, 0, 1);
    // out = gated @ V3^T, split-K=2 -> partials in C1 (free by now), then reduce
    rung(fn, 1, Uh, Ul, V3h, V3l, C1, nullptr, nullptr, nullptr,
         M, D, F, 1, (long long)F * M, (long long)F * D, (long long)M * D, F / 2, 2);
    red2_k<<<2048, 256>>>((const float4*)C1, (float4*)d_out, (M * D) / 4);
}

// round 10
// speedup vs baseline: 1.0136x; 1.0136x over previous
#include <cuda_runtime.h>
#include <cuda.h>
#include <cuda_bf16.h>
#include <math.h>
#include <stdint.h>

// ===========================================================================
// R9: wave-quantization fixes. Engine unchanged (bf16x3 mma.sync + TMA).
//  - fold launch z=5: V3^T full-K + V1,V2 split-K2 (partials -> g_c1)
//  - out GEMM split-K4 + deterministic red4
//  - tsplit with 128B paired bf16 stores
// ===========================================================================

#define TILE_B 8192              // one 128x32 bf16 tile in smem (bytes)
#define STAGE_B 32768            // 4 tiles (Ah,Al,Bh,Bl)
#define SMEM_TOT (1024 + 1024 + 3 * STAGE_B)

__device__ __forceinline__ uint32_t smem_u32(const void* p) {
    uint32_t a;
    asm("{ .reg .u64 t; cvta.to.shared.u64 t, %1; cvt.u32.u64 %0, t; }" : "=r"(a) : "l"(p));
    return a;
}
#define MBARRIER_INIT(a, c) \
    asm volatile("mbarrier.init.shared.b64 [%0], %1;" :: "r"((uint32_t)(a)), "r"((uint32_t)(c)) : "memory")
#define MBARRIER_EXPECT_TX(a, b) \
    asm volatile("mbarrier.arrive.expect_tx.shared.b64 _, [%0], %1;" :: "r"((uint32_t)(a)), "r"((uint32_t)(b)) : "memory")
#define MBARRIER_WAIT_PARITY(a, p) do { \
    uint32_t _m = (uint32_t)(a), _p = (uint32_t)(p), _d; \
    asm volatile("{\n\t.reg .pred q;\n\t" \
        "mbarrier.try_wait.parity.acquire.cta.shared::cta.b64 q, [%1], %2;\n\t" \
        "selp.b32 %0, 1, 0, q;\n\t}" : "=r"(_d) : "r"(_m), "r"(_p) : "memory"); \
    if (!_d) { \
        asm volatile("{\n\t.reg .pred Q;\n\t" \
            "WL_%=:\n\t" \
            "mbarrier.try_wait.parity.acquire.cta.shared::cta.b64 Q, [%0], %1, 0x989680;\n\t" \
            "@Q bra.uni WD_%=;\n\t" \
            "bra.uni WL_%=;\n\t" \
            "WD_%=:\n\t}" :: "r"(_m), "r"(_p) : "memory"); \
    } \
} while (0)
#define TMA_LOAD_3D(sa, tm, cx, cy, cz, mb) \
    asm volatile("cp.async.bulk.tensor.3d.shared::cta.global.tile.mbarrier::complete_tx::bytes " \
        "[%0], [%1, {%2, %3, %4}], [%5];" \
        :: "r"((uint32_t)(sa)), "l"(tm), "r"((int32_t)(cx)), "r"((int32_t)(cy)), \
           "r"((int32_t)(cz)), "r"((uint32_t)(mb)) : "memory")
#define LDSM4(R, a) \
    asm volatile("ldmatrix.sync.aligned.m8n8.x4.shared.b16 {%0,%1,%2,%3}, [%4];" \
        : "=r"((R)[0]), "=r"((R)[1]), "=r"((R)[2]), "=r"((R)[3]) : "r"(a))

__device__ __forceinline__ void mma_bf16(float* c, const uint32_t* a, uint32_t b0, uint32_t b1) {
    asm volatile(
        "mma.sync.aligned.m16n8k16.row.col.f32.bf16.bf16.f32 "
        "{%0,%1,%2,%3}, {%4,%5,%6,%7}, {%8,%9}, {%0,%1,%2,%3};"
        : "+f"(c[0]), "+f"(c[1]), "+f"(c[2]), "+f"(c[3])
        : "r"(a[0]), "r"(a[1]), "r"(a[2]), "r"(a[3]), "r"(b0), "r"(b1));
}

// 16B XOR swizzle within a [rows x 32] bf16 tile (== TMA SWIZZLE_64B).
__device__ __forceinline__ uint32_t sw(int row, int col16) {
    return (uint32_t)(row * 64 + ((col16 ^ ((row >> 1) & 3)) << 4));
}

// EPI 1: fp32 write Cf.   EPI 2: v = OTH*silu(acc), split-write Ch/Cl.
// EPI 3: fold-hybrid — z==0 split-write Ch/Cl (full K); z>=1 fp32 partials.
// zmode 0: z = batch coord (TMA z).  zmode 1: split-K (k0 = z*kz).
// zmode 2: fold-hybrid (z0 full-K batch0; z1..4 = batch1,2 K-halves).
template <int EPI>
__global__ __launch_bounds__(256, 2) void gemm_b3(
    const __grid_constant__ CUtensorMap tAh, const __grid_constant__ CUtensorMap tAl,
    const __grid_constant__ CUtensorMap tBh, const __grid_constant__ CUtensorMap tBl,
    float* __restrict__ Cf, __nv_bfloat16* __restrict__ Ch, __nv_bfloat16* __restrict__ Cl,
    const float* __restrict__ OTH, int M, int N, int K,
    long long czs, int kz, int zmode)
{
    extern __shared__ char smem[];
    const uint32_t sb0 = smem_u32(smem);
    const uint32_t sb = (sb0 + 1023) & ~1023u;
    const int tid = threadIdx.x;
    const int z = blockIdx.z;

    int cz, k00, Keff;
    bool splitout = false;
    if (zmode == 1) {
        cz = 0; k00 = z * kz; Keff = kz;
        Cf += (size_t)z * czs;
    } else if (zmode == 2) {
        cz = (z + 1) >> 1;
        if (z == 0) { k00 = 0; Keff = K; splitout = true; }
        else { k00 = ((z + 1) & 1) * kz; Keff = kz; Cf += (size_t)(z - 1) * czs; }
    } else {
        cz = z; k00 = 0; Keff = K;
        if (Cf) Cf += (size_t)z * czs;
        if (Ch) { Ch += (size_t)z * czs; Cl += (size_t)z * czs; }
    }

    // ---- L2-friendly CTA rasterization (GROUP_M = 16), per z-slice ----
    const int gn = gridDim.x, gm = gridDim.y;
    const int bid = blockIdx.y * gn + blockIdx.x;
    const int npg = 16 * gn;
    const int gid = bid / npg;
    const int fm = gid * 16;
    const int gs = (gm - fm < 16) ? (gm - fm) : 16;
    const int bm = (fm + (bid % gs)) * 128;
    const int bn = ((bid % npg) / gs) * 128;

    const int w = tid >> 5, lane = tid & 31;
    const int wm = (w >> 2) * 64, wn = (w & 3) * 32;
    const int jj = lane >> 3, rr = lane & 7;
    const int aR = (jj & 1) * 8 + rr, aC16 = jj >> 1;
    const int bR = (jj >> 1) * 8 + rr, bC16 = jj & 1;

    const uint32_t bars = sb;
    const uint32_t stg0 = sb + 1024;

    if (tid == 0) {
        MBARRIER_INIT(bars + 0, 1);
        MBARRIER_INIT(bars + 8, 1);
        MBARRIER_INIT(bars + 16, 1);
    }
    __syncthreads();

    const int nst = Keff / 32;

    if (tid == 0) {
#pragma unroll
        for (int s = 0; s < 3; s++) {
            const uint32_t bar = bars + s * 8;
            const uint32_t stb = stg0 + s * STAGE_B;
            const int k0 = k00 + s * 32;
            MBARRIER_EXPECT_TX(bar, STAGE_B);
            TMA_LOAD_3D(stb,              &tAh, k0, bm, cz, bar);
            TMA_LOAD_3D(stb + TILE_B,     &tAl, k0, bm, cz, bar);
            TMA_LOAD_3D(stb + 2 * TILE_B, &tBh, k0, bn, cz, bar);
            TMA_LOAD_3D(stb + 3 * TILE_B, &tBl, k0, bn, cz, bar);
        }
    }

    float c[4][4][4];
#pragma unroll
    for (int mi = 0; mi < 4; mi++)
#pragma unroll
        for (int ni = 0; ni < 4; ni++)
#pragma unroll
            for (int q = 0; q < 4; q++) c[mi][ni][q] = 0.0f;

    for (int t = 0; t < nst; t++) {
        const int buf = t % 3;
        MBARRIER_WAIT_PARITY(bars + buf * 8, (t / 3) & 1);

        const uint32_t stb = stg0 + (uint32_t)buf * STAGE_B;
#pragma unroll
        for (int ks = 0; ks < 2; ks++) {
            uint32_t af[4][4], bhf[2][4], blf[2][4];
#pragma unroll
            for (int mi = 0; mi < 4; mi++)
                LDSM4(af[mi], stb + sw(wm + mi * 16 + aR, ks * 2 + aC16));
#pragma unroll
            for (int np = 0; np < 2; np++) {
                const uint32_t bd = stb + 2 * TILE_B + sw(wn + np * 16 + bR, ks * 2 + bC16);
                LDSM4(bhf[np], bd);
                LDSM4(blf[np], bd + TILE_B);
            }
#pragma unroll
            for (int mi = 0; mi < 4; mi++)
#pragma unroll
                for (int ni = 0; ni < 4; ni++) {
                    const int p = ni >> 1, q = (ni & 1) * 2;
                    mma_bf16(c[mi][ni], af[mi], bhf[p][q], bhf[p][q + 1]);
                    mma_bf16(c[mi][ni], af[mi], blf[p][q], blf[p][q + 1]);
                }
#pragma unroll
            for (int mi = 0; mi < 4; mi++)
                LDSM4(af[mi], stb + TILE_B + sw(wm + mi * 16 + aR, ks * 2 + aC16));
#pragma unroll
            for (int mi = 0; mi < 4; mi++)
#pragma unroll
                for (int ni = 0; ni < 4; ni++) {
                    const int p = ni >> 1, q = (ni & 1) * 2;
                    mma_bf16(c[mi][ni], af[mi], bhf[p][q], bhf[p][q + 1]);
                }
        }

        __syncthreads();
        if (t + 3 < nst && tid == 0) {
            const uint32_t bar = bars + buf * 8;
            const int k0 = k00 + (t + 3) * 32;
            MBARRIER_EXPECT_TX(bar, STAGE_B);
            TMA_LOAD_3D(stb,              &tAh, k0, bm, cz, bar);
            TMA_LOAD_3D(stb + TILE_B,     &tAl, k0, bm, cz, bar);
            TMA_LOAD_3D(stb + 2 * TILE_B, &tBh, k0, bn, cz, bar);
            TMA_LOAD_3D(stb + 3 * TILE_B, &tBl, k0, bn, cz, bar);
        }
    }

    // ---- epilogue ----
#pragma unroll
    for (int mi = 0; mi < 4; mi++)
#pragma unroll
        for (int ni = 0; ni < 4; ni++) {
            const int r0 = bm + wm + mi * 16 + (lane >> 2);
            const int col = bn + wn + ni * 8 + (lane & 3) * 2;
            const size_t o0 = (size_t)r0 * N + col;
            const size_t o1 = (size_t)(r0 + 8) * N + col;
            float v0 = c[mi][ni][0], v1 = c[mi][ni][1];
            float v2 = c[mi][ni][2], v3 = c[mi][ni][3];
            if (EPI == 2) {
                const float2 u0 = *(const float2*)(OTH + o0);
                const float2 u1 = *(const float2*)(OTH + o1);
                v0 = u0.x * (v0 / (1.0f + expf(-v0)));
                v1 = u0.y * (v1 / (1.0f + expf(-v1)));
                v2 = u1.x * (v2 / (1.0f + expf(-v2)));
                v3 = u1.y * (v3 / (1.0f + expf(-v3)));
            }
            const bool wr_split = (EPI == 2) || (EPI == 3 && splitout);
            if (wr_split) {
                __nv_bfloat162 hh, ll;
                hh.x = __float2bfloat16(v0); hh.y = __float2bfloat16(v1);
                ll.x = __float2bfloat16(v0 - __bfloat162float(hh.x));
                ll.y = __float2bfloat16(v1 - __bfloat162float(hh.y));
                *(__nv_bfloat162*)(Ch + o0) = hh;
                *(__nv_bfloat162*)(Cl + o0) = ll;
                hh.x = __float2bfloat16(v2); hh.y = __float2bfloat16(v3);
                ll.x = __float2bfloat16(v2 - __bfloat162float(hh.x));
                ll.y = __float2bfloat16(v3 - __bfloat162float(hh.y));
                *(__nv_bfloat162*)(Ch + o1) = hh;
                *(__nv_bfloat162*)(Cl + o1) = ll;
            } else {
                *(float2*)(Cf + o0) = make_float2(v0, v1);
                *(float2*)(Cf + o1) = make_float2(v2, v3);
            }
        }
}

// ===========================================================================
// scratch (static; no allocations).
// ===========================================================================
#define MDE 16777216ll
#define FFE 67108864ll
__device__ __nv_bfloat16 g_bf[805306368];   // 16 MDE + 8 FFE exactly
__device__ float g_c1[67108864];

// ---- pre-pass: fp32 -> (bf16 hi, bf16 lo) ----
struct bf4 { __nv_bfloat162 a, b; };
__global__ void split_k(const float4* __restrict__ in, bf4* __restrict__ hi,
                        bf4* __restrict__ lo, int n4) {
    for (int i = blockIdx.x * blockDim.x + threadIdx.x; i < n4; i += gridDim.x * blockDim.x) {
        const float4 v = in[i];
        bf4 H, L;
        H.a.x = __float2bfloat16(v.x); H.a.y = __float2bfloat16(v.y);
        H.b.x = __float2bfloat16(v.z); H.b.y = __float2bfloat16(v.w);
        L.a.x = __float2bfloat16(v.x - __bfloat162float(H.a.x));
        L.a.y = __float2bfloat16(v.y - __bfloat162float(H.a.y));
        L.b.x = __float2bfloat16(v.z - __bfloat162float(H.b.x));
        L.b.y = __float2bfloat16(v.w - __bfloat162float(H.b.y));
        hi[i] = H; lo[i] = L;
    }
}
// transpose + split with 128B paired stores: in [R,C] fp32 -> out [C,R] bf16 pair
__global__ void tsplit_k(const float* __restrict__ in, __nv_bfloat16* __restrict__ hi,
                         __nv_bfloat16* __restrict__ lo, int R, int C) {
    __shared__ float t[64][33];
    const int c0 = blockIdx.x * 32, r0 = blockIdx.y * 64;
#pragma unroll
    for (int i = 0; i < 8; i++) {
        const int row = threadIdx.y + i * 8;
        t[row][threadIdx.x] = in[(size_t)(r0 + row) * C + c0 + threadIdx.x];
    }
    __syncthreads();
#pragma unroll
    for (int j = 0; j < 4; j++) {
        const int cc = threadIdx.y + j * 8;
        const int rr = threadIdx.x * 2;
        const float v0 = t[rr][cc], v1 = t[rr + 1][cc];
        __nv_bfloat162 hh, ll;
        hh.x = __float2bfloat16(v0); hh.y = __float2bfloat16(v1);
        ll.x = __float2bfloat16(v0 - __bfloat162float(hh.x));
        ll.y = __float2bfloat16(v1 - __bfloat162float(hh.y));
        const size_t o = (size_t)(c0 + cc) * R + r0 + rr;
        *(__nv_bfloat162*)(hi + o) = hh;
        *(__nv_bfloat162*)(lo + o) = ll;
    }
}
// bf16 pair transpose: a,b [R,C] -> oa,ob [C,R]
__global__ void tpose2_k(const __nv_bfloat16* __restrict__ a, const __nv_bfloat16* __restrict__ b,
                         __nv_bfloat16* __restrict__ oa, __nv_bfloat16* __restrict__ ob,
                         int R, int C) {
    __shared__ __nv_bfloat16 t[2][32][33];
    const int c0 = blockIdx.x * 32, r0 = blockIdx.y * 32;
#pragma unroll
    for (int i = 0; i < 32; i += 8) {
        const size_t src = (size_t)(r0 + threadIdx.y + i) * C + c0 + threadIdx.x;
        t[0][threadIdx.y + i][threadIdx.x] = a[src];
        t[1][threadIdx.y + i][threadIdx.x] = b[src];
    }
    __syncthreads();
#pragma unroll
    for (int i = 0; i < 32; i += 8) {
        const size_t o = (size_t)(c0 + threadIdx.y + i) * R + r0 + threadIdx.x;
        oa[o] = t[0][threadIdx.x][threadIdx.y + i];
        ob[o] = t[1][threadIdx.x][threadIdx.y + i];
    }
}
// reduce 2 K-half partials and split -> V_b (b = blockIdx.y in {0,1})
__global__ void rsplit2_k(const float4* __restrict__ p, bf4* __restrict__ vh,
                          bf4* __restrict__ vl, int n4) {
    const int b = blockIdx.y;
    const float4* pa = p + (size_t)b * 2 * n4;
    bf4* oh = vh + (size_t)b * 2 * n4;
    bf4* ol = vl + (size_t)b * 2 * n4;
    for (int i = blockIdx.x * blockDim.x + threadIdx.x; i < n4; i += gridDim.x * blockDim.x) {
        const float4 x = pa[i], y = pa[i + n4];
        const float4 s = make_float4(x.x + y.x, x.y + y.y, x.z + y.z, x.w + y.w);
        bf4 H, L;
        H.a.x = __float2bfloat16(s.x); H.a.y = __float2bfloat16(s.y);
        H.b.x = __float2bfloat16(s.z); H.b.y = __float2bfloat16(s.w);
        L.a.x = __float2bfloat16(s.x - __bfloat162float(H.a.x));
        L.a.y = __float2bfloat16(s.y - __bfloat162float(H.a.y));
        L.b.x = __float2bfloat16(s.z - __bfloat162float(H.b.x));
        L.b.y = __float2bfloat16(s.w - __bfloat162float(H.b.y));
        oh[i] = H; ol[i] = L;
    }
}
// reduce 4 split-K partials (fixed order, deterministic)
__global__ void red4_k(const float4* __restrict__ p, float4* __restrict__ o, int n4) {
    for (int i = blockIdx.x * blockDim.x + threadIdx.x; i < n4; i += gridDim.x * blockDim.x) {
        const float4 a = p[i], b = p[i + n4], c = p[i + 2 * n4], d = p[i + 3 * n4];
        o[i] = make_float4(((a.x + b.x) + c.x) + d.x, ((a.y + b.y) + c.y) + d.y,
                           ((a.z + b.z) + c.z) + d.z, ((a.w + b.w) + c.w) + d.w);
    }
}

// ===========================================================================
typedef CUresult (*PFN_enc)(CUtensorMap*, CUtensorMapDataType, cuuint32_t, void*,
                            const cuuint64_t*, const cuuint64_t*, const cuuint32_t*,
                            const cuuint32_t*, CUtensorMapInterleave, CUtensorMapSwizzle,
                            CUtensorMapL2promotion, CUtensorMapFloatOOBfill);

static void enc_map(PFN_enc fn, CUtensorMap* m, const __nv_bfloat16* p, int K, int rows,
                    int nz, long long zelems) {
    cuuint64_t dims[3] = {(cuuint64_t)K, (cuuint64_t)rows, (cuuint64_t)nz};
    cuuint64_t str[2] = {(cuuint64_t)K * 2, (cuuint64_t)zelems * 2};
    cuuint32_t box[3] = {32, 128, 1};
    cuuint32_t es[3] = {1, 1, 1};
    fn(m, CU_TENSOR_MAP_DATA_TYPE_BFLOAT16, 3, (void*)p, dims, str, box, es,
       CU_TENSOR_MAP_INTERLEAVE_NONE, CU_TENSOR_MAP_SWIZZLE_64B,
       CU_TENSOR_MAP_L2_PROMOTION_L2_128B, CU_TENSOR_MAP_FLOAT_OOB_FILL_NONE);
}

static void rung(PFN_enc fn, int epi,
                 const __nv_bfloat16* Ah, const __nv_bfloat16* Al,
                 const __nv_bfloat16* Bh, const __nv_bfloat16* Bl,
                 float* Cf, __nv_bfloat16* Ch, __nv_bfloat16* Cl,
                 const float* OTH, int M, int N, int K,
                 int nz, long long zsA, long long zsB, long long czs,
                 int kz, int zmode, int gz)
{
    CUtensorMap ma, mal, mb, mbl;
    enc_map(fn, &ma, Ah, K, M, nz, zsA);  enc_map(fn, &mal, Al, K, M, nz, zsA);
    enc_map(fn, &mb, Bh, K, N, nz, zsB);  enc_map(fn, &mbl, Bl, K, N, nz, zsB);
    const dim3 g(N / 128, M / 128, gz), b(256);
    if (epi == 1) {
        cudaFuncSetAttribute(gemm_b3<1>, cudaFuncAttributeMaxDynamicSharedMemorySize, SMEM_TOT);
        gemm_b3<1><<<g, b, SMEM_TOT>>>(ma, mal, mb, mbl, Cf, Ch, Cl, OTH, M, N, K, czs, kz, zmode);
    } else if (epi == 2) {
        cudaFuncSetAttribute(gemm_b3<2>, cudaFuncAttributeMaxDynamicSharedMemorySize, SMEM_TOT);
        gemm_b3<2><<<g, b, SMEM_TOT>>>(ma, mal, mb, mbl, Cf, Ch, Cl, OTH, M, N, K, czs, kz, zmode);
    } else {
        cudaFuncSetAttribute(gemm_b3<3>, cudaFuncAttributeMaxDynamicSharedMemorySize, SMEM_TOT);
        gemm_b3<3><<<g, b, SMEM_TOT>>>(ma, mal, mb, mbl, Cf, Ch, Cl, OTH, M, N, K, czs, kz, zmode);
    }
}

extern "C" void kernel_launch(void* const* d_in, const int* in_sizes, int n_in,
                              void* d_out, int out_size)
{
    const float* x  = (const float*)d_in[0];
    const float* wu = (const float*)d_in[1];
    const float* wg = (const float*)d_in[2];
    const float* wd = (const float*)d_in[3];
    const float* h1 = (const float*)d_in[4];   // h_up_T   [F,F]
    const float* h2 = (const float*)d_in[5];   // h_gate_T [F,F]
    const float* h3 = (const float*)d_in[6];   // h_down   [F,F]

    int F = 1;
    while ((long long)(F + 1) * (F + 1) <= (long long)in_sizes[4]) F++;
    const int D = in_sizes[1] / F;
    const int M = in_sizes[0] / D;

    __nv_bfloat16* bb;
    float* C1;
    cudaGetSymbolAddress((void**)&bb, g_bf);
    cudaGetSymbolAddress((void**)&C1, g_c1);

    // slab layout (16 MDE + 8 FFE, exact fit)
    __nv_bfloat16 *xh   = bb,             *xl   = bb + MDE;
    __nv_bfloat16 *wdh  = bb + 2 * MDE,   *wuth = bb + 3 * MDE,  *wgth = bb + 4 * MDE;
    __nv_bfloat16 *wdl  = bb + 5 * MDE,   *wutl = bb + 6 * MDE,  *wgtl = bb + 7 * MDE;
    __nv_bfloat16 *V1h  = bb + 8 * MDE,   *V1l  = bb + 9 * MDE;
    __nv_bfloat16 *V2h  = bb + 10 * MDE,  *V2l  = bb + 11 * MDE;
    __nv_bfloat16 *V3h  = bb + 12 * MDE,  *V3l  = bb + 13 * MDE;   // V3 [D,F]
    __nv_bfloat16 *V3th = bb + 14 * MDE,  *V3tl = bb + 15 * MDE;   // V3^T [F,D]
    __nv_bfloat16* hb   = bb + 16 * MDE;
    __nv_bfloat16 *hdh  = hb,             *h1th = hb + FFE,      *h2th = hb + 2 * FFE;
    __nv_bfloat16 *hdl  = hb + 3 * FFE,   *h1tl = hb + 4 * FFE,  *h2tl = hb + 5 * FFE;
    __nv_bfloat16 *Uh   = hb + 6 * FFE,   *Ul   = hb + 7 * FFE;

    // ---- prepass ----
    split_k<<<2048, 256>>>((const float4*)x,  (bf4*)xh,  (bf4*)xl,  (M * D) / 4);
    split_k<<<2048, 256>>>((const float4*)wd, (bf4*)wdh, (bf4*)wdl, (D * F) / 4);
    split_k<<<2048, 256>>>((const float4*)h3, (bf4*)hdh, (bf4*)hdl, (F * F) / 4);
    const dim3 tb(32, 8);
    tsplit_k<<<dim3(F / 32, F / 64), tb>>>(h1, h1th, h1tl, F, F);
    tsplit_k<<<dim3(F / 32, F / 64), tb>>>(h2, h2th, h2tl, F, F);
    tsplit_k<<<dim3(D / 32, F / 64), tb>>>(wu, wuth, wutl, F, D);
    tsplit_k<<<dim3(D / 32, F / 64), tb>>>(wg, wgth, wgtl, F, D);

    PFN_enc fn = nullptr;
    cudaDriverEntryPointQueryResult qr;
    cudaGetDriverEntryPoint("cuTensorMapEncodeTiled", (void**)&fn, cudaEnableDefault, &qr);

    const long long FD = (long long)F * D;

    // ---- fold launch z=5: z0 = V3^T full-K (batch0 = hd/wd), z1..4 = V1,V2 K-halves ----
    // A planes [hd][h1t][h2t] stride FFE; B planes [wd][wut][wgt] stride MDE.
    rung(fn, 3, hdh, hdl, wdh, wdl, C1, V3th, V3tl, nullptr,
         F, D, F, 3, FFE, MDE, FD, F / 2, 2, 5);

    // V1 = p0+p1, V2 = p2+p3 (split-write)
    rsplit2_k<<<dim3(2048, 2), 256>>>((const float4*)C1, (bf4*)V1h, (bf4*)V1l, (int)(FD / 4));
    // V3 = transpose(V3^T)
    tpose2_k<<<dim3(D / 32, F / 32), tb>>>(V3th, V3tl, V3h, V3l, F, D);

    // ---- activation GEMMs ----
    // up2 = x @ V1^T -> C1 (fp32)
    rung(fn, 1, xh, xl, V1h, V1l, C1, nullptr, nullptr, nullptr,
         M, F, D, 1, MDE, MDE, 0, 0, 0, 1);
    // gated = C1 * silu(x @ V2^T) -> split U
    rung(fn, 2, xh, xl, V2h, V2l, nullptr, Uh, Ul, C1,
         M, F, D, 1, MDE, MDE, 0, 0, 0, 1);
    // out = gated @ V3^T, split-K4 -> partials in C1, then deterministic reduce
    rung(fn, 1, Uh, Ul, V3h, V3l, C1, nullptr, nullptr, nullptr,
         M, D, F, 1, FFE, MDE, (long long)M * D, F / 4, 1, 4);
    red4_k<<<2048, 256>>>((const float4*)C1, (float4*)d_out, (M * D) / 4);
}